// round 12
// baseline (speedup 1.0000x reference)
#include <cuda_runtime.h>
#include <cstdint>

// GatherBlock: out[m, :, :, :] = x[b[m], :, yb[m]*16 : yb[m]*16+16, xb[m]*16 : xb[m]*16+16]
// x: (8, 64, 256, 256) fp32, indices: (1024, 3) int32, out: (1024, 64, 16, 16) fp32.
//
// R12: persistent double-buffered copy loop. Previous kernels burst N loads,
// drain, burst N stores, exit — the read pipe idles during every store phase
// (DRAM stuck ~57%, nothing saturated). Here 1024 persistent CTAs (one full
// wave) each walk 8 tile-sorted 8KB chunks with a 2-stage register pipeline:
// loads for chunk j+1 are in flight while chunk j stores drain. Keeps the
// ~free counting-sort schedule, __ldcg reads, __stcs streaming stores.

static constexpr int C = 64;
static constexpr int H = 256;
static constexpr int W = 256;
static constexpr int BH = 16;
static constexpr int BW = 16;
static constexpr int CHW = C * H * W;      // 4194304
static constexpr int HW = H * W;           // 65536
static constexpr int VEC_PER_M = C * BH * BW / 4;     // 4096 float4 per output block
static constexpr int SPLIT = 8;                       // chunks per m
static constexpr int VEC_PER_CHUNK = VEC_PER_M / SPLIT; // 512 float4 per chunk
static constexpr int M_MAX = 1024;
static constexpr int BINS = 2048;                     // 8*16*16 tile ids
static constexpr int TPB = 128;                       // threads per CTA
static constexpr int LPT = VEC_PER_CHUNK / TPB;       // 4 float4 per thread per chunk
static constexpr int GRID = 1024;                     // persistent CTAs (one wave)

__device__ int g_perm[M_MAX];

__global__ __launch_bounds__(M_MAX, 1)
void sort_indices_kernel(const int* __restrict__ idx, int M)
{
    __shared__ unsigned hist[BINS];
    __shared__ unsigned warpsum[32];

    const int t = threadIdx.x;
    const int lane = t & 31;
    const int wid = t >> 5;

    hist[2 * t]     = 0;
    hist[2 * t + 1] = 0;
    __syncthreads();

    int key = 0;
    if (t < M) {
        const int b  = idx[3 * t + 0];
        const int yb = idx[3 * t + 1];
        const int xb = idx[3 * t + 2];
        key = (b << 8) | (yb << 4) | xb;   // 11 bits
        atomicAdd(&hist[key], 1u);
    }
    __syncthreads();

    const unsigned a = hist[2 * t];
    const unsigned bcnt = hist[2 * t + 1];
    const unsigned s = a + bcnt;

    unsigned incl = s;
#pragma unroll
    for (int d = 1; d < 32; d <<= 1) {
        const unsigned n = __shfl_up_sync(0xFFFFFFFFu, incl, d);
        if (lane >= d) incl += n;
    }
    const unsigned thr_excl = incl - s;
    if (lane == 31) warpsum[wid] = incl;
    __syncthreads();

    if (wid == 0) {
        unsigned v = warpsum[lane];
        unsigned pv = v;
#pragma unroll
        for (int d = 1; d < 32; d <<= 1) {
            const unsigned n = __shfl_up_sync(0xFFFFFFFFu, pv, d);
            if (lane >= d) pv += n;
        }
        warpsum[lane] = pv - v;
    }
    __syncthreads();

    const unsigned base = warpsum[wid] + thr_excl;
    hist[2 * t]     = base;
    hist[2 * t + 1] = base + a;
    __syncthreads();

    if (t < M) {
        const unsigned pos = atomicAdd(&hist[key], 1u);
        g_perm[pos] = t;
    }
}

struct ChunkPtrs {
    const float* src;   // tile base in x
    float4* dst;        // chunk base in out (dst of v0)
    int v0;             // first float4 index within the block for this thread
};

__device__ __forceinline__ ChunkPtrs chunk_ptrs(
    const float* __restrict__ x, const int* __restrict__ idx,
    float4* __restrict__ out, int j, int t)
{
    const int m = g_perm[j >> 3];
    const int q = j & 7;
    const int b  = idx[3 * m + 0];
    const int yb = idx[3 * m + 1];
    const int xb = idx[3 * m + 2];
    ChunkPtrs p;
    p.src = x + (size_t)b * CHW + (size_t)(yb * BH) * W + (size_t)(xb * BW);
    p.v0  = q * VEC_PER_CHUNK + t;
    p.dst = out + (size_t)m * VEC_PER_M;
    return p;
}

__device__ __forceinline__ void load_chunk(const ChunkPtrs& p, float4 r[LPT])
{
#pragma unroll
    for (int k = 0; k < LPT; k++) {
        const int v = p.v0 + k * TPB;
        const int c = v >> 6;
        const int i = (v >> 2) & 15;
        const int jj = v & 3;
        const float4* s = reinterpret_cast<const float4*>(
            p.src + (size_t)c * HW + (size_t)i * W) + jj;
        r[k] = __ldcg(s);
    }
}

__device__ __forceinline__ void store_chunk(const ChunkPtrs& p, const float4 r[LPT])
{
#pragma unroll
    for (int k = 0; k < LPT; k++) {
        __stcs(p.dst + p.v0 + k * TPB, r[k]);
    }
}

__global__ __launch_bounds__(TPB, 8)
void gather_block_kernel(const float* __restrict__ x,
                         const int* __restrict__ idx,
                         float4* __restrict__ out)
{
    const int t = threadIdx.x;
    const int total = M_MAX * SPLIT;   // 8192 chunks

    int j0 = blockIdx.x;
    ChunkPtrs p0 = chunk_ptrs(x, idx, out, j0, t);
    float4 a[LPT], b[LPT];
    load_chunk(p0, a);

    for (;;) {
        const int j1 = j0 + GRID;
        if (j1 < total) {
            ChunkPtrs p1 = chunk_ptrs(x, idx, out, j1, t);
            load_chunk(p1, b);          // loads for j1 in flight...
            store_chunk(p0, a);         // ...while j0 stores drain

            const int j2 = j1 + GRID;
            if (j2 < total) {
                ChunkPtrs p2 = chunk_ptrs(x, idx, out, j2, t);
                load_chunk(p2, a);
                store_chunk(p1, b);
                j0 = j2;
                p0 = p2;
                continue;
            }
            store_chunk(p1, b);
            return;
        }
        store_chunk(p0, a);
        return;
    }
}

extern "C" void kernel_launch(void* const* d_in, const int* in_sizes, int n_in,
                              void* d_out, int out_size)
{
    const float* x  = (const float*)d_in[0];
    const int* idx  = (const int*)d_in[1];
    float4* out     = (float4*)d_out;

    const int M = in_sizes[1] / 3;  // 1024
    sort_indices_kernel<<<1, M_MAX>>>(idx, M);
    gather_block_kernel<<<GRID, TPB>>>(x, idx, out);
}